// round 3
// baseline (speedup 1.0000x reference)
#include <cuda_runtime.h>

#define D_MODEL 1024
#define NUM_HEADS 16
#define DK 64
#define SEQ 2048
#define BATCH 2

// Scratch (allocation-free: __device__ globals)
__device__ float g_qh[BATCH * NUM_HEADS * SEQ * DK];
__device__ float g_kh[BATCH * NUM_HEADS * SEQ * DK];
__device__ float g_vh[BATCH * NUM_HEADS * SEQ * DK];
__device__ float g_ctx[BATCH * SEQ * D_MODEL];

// ---------------------------------------------------------------------------
// NT GEMM: C[m,n] = sum_k A[m,k] * W[n,k] + bias[n]
// headScatter=1: scatter output into [B,H,S,DK] layout.
// Tiles 64x64x32, 256 threads, 4x4 micro-tile per thread, float4 smem reads.
// ---------------------------------------------------------------------------
#define BM 64
#define BN 64
#define BK 32
#define GSTR (BM + 4)

__global__ void __launch_bounds__(256)
gemm_nt(const float* __restrict__ A, const float* __restrict__ W,
        const float* __restrict__ bias, float* __restrict__ C,
        int M, int N, int K, int headScatter) {
    __shared__ __align__(16) float As[BK * GSTR];
    __shared__ __align__(16) float Bs[BK * GSTR];

    const int tid = threadIdx.x;
    const int tx = tid & 15;
    const int ty = tid >> 4;
    const int mBase = blockIdx.x * BM;
    const int nBase = blockIdx.y * BN;

    const float* Ap = A + (size_t)mBase * K;
    const float* Wp = W + (size_t)nBase * K;

    float acc[4][4];
#pragma unroll
    for (int i = 0; i < 4; i++)
#pragma unroll
        for (int j = 0; j < 4; j++) acc[i][j] = 0.0f;

    const int lkk = tid & 31;       // k within tile
    const int lr = tid >> 5;        // row group (0..7)

    for (int k0 = 0; k0 < K; k0 += BK) {
#pragma unroll
        for (int p = 0; p < 8; p++) {
            int r = lr + p * 8;
            As[lkk * GSTR + r] = Ap[(size_t)r * K + k0 + lkk];
            Bs[lkk * GSTR + r] = Wp[(size_t)r * K + k0 + lkk];
        }
        __syncthreads();

#pragma unroll
        for (int kk = 0; kk < BK; kk++) {
            float4 a4 = *(const float4*)&As[kk * GSTR + ty * 4];
            float4 b4 = *(const float4*)&Bs[kk * GSTR + tx * 4];
            float a[4] = {a4.x, a4.y, a4.z, a4.w};
            float b[4] = {b4.x, b4.y, b4.z, b4.w};
#pragma unroll
            for (int i = 0; i < 4; i++)
#pragma unroll
                for (int j = 0; j < 4; j++) acc[i][j] += a[i] * b[j];
        }
        __syncthreads();
    }

#pragma unroll
    for (int j = 0; j < 4; j++) {
        int n = nBase + tx * 4 + j;
        float bv = bias[n];
#pragma unroll
        for (int i = 0; i < 4; i++) {
            int m = mBase + ty * 4 + i;
            float v = acc[i][j] + bv;
            if (headScatter) {
                int b = m / SEQ, s = m % SEQ;
                int h = n / DK, d = n % DK;
                g_qh[0];  // no-op to keep symbol referenced semantics (optimized away)
                C[(((size_t)b * NUM_HEADS + h) * SEQ + s) * DK + d] = v;
            } else {
                C[(size_t)m * N + n] = v;
            }
        }
    }
}

// ---------------------------------------------------------------------------
// Flash-attention style kernel.
// grid: (SEQ/64, BATCH*NUM_HEADS), 256 threads.
// Block handles 64 queries for one (b,h); loops over 32 K-tiles of 64 keys.
// Online softmax; two 64x64x64 smem GEMMs per tile (QK^T and P@V),
// 4x4 register micro-tiles, float4 LDS via transposed pad-4 layouts.
// ---------------------------------------------------------------------------
#define ASTR 68   // 64 + 4 pad -> float4-aligned rows, conflict-free reads

__global__ void __launch_bounds__(256)
attn_kernel(const float* __restrict__ Qh, const float* __restrict__ Kh,
            const float* __restrict__ Vh, const int* __restrict__ mask,
            float* __restrict__ ctx) {
    extern __shared__ __align__(16) float sm[];
    float* Qs = sm;                   // [64 d][68]  Qs[d*ASTR + row]
    float* Ks = sm + 64 * ASTR;       // [64 d][68]  Ks[d*ASTR + col]; reused as Ps[kc][row]
    float* Vs = sm + 2 * 64 * ASTR;   // [64 kc][68] Vs[kc*ASTR + d]
    float* mk = sm + 3 * 64 * ASTR;   // [64] additive mask

    const int tid = threadIdx.x;
    const int tx = tid & 15;
    const int ty = tid >> 4;
    const int bh = blockIdx.y;
    const int b = bh >> 4;
    const int h = bh & 15;
    const int qbase = blockIdx.x * 64;

    const float* Qp = Qh + (size_t)bh * SEQ * DK + (size_t)qbase * DK;
    const float* Kp = Kh + (size_t)bh * SEQ * DK;
    const float* Vp = Vh + (size_t)bh * SEQ * DK;

    // Load Q tile transposed: Qs[d][row]
#pragma unroll
    for (int p = 0; p < 16; p++) {
        int idx = tid + p * 256;
        int r = idx >> 6, d = idx & 63;
        Qs[d * ASTR + r] = Qp[idx];
    }

    float m_i[4], l_i[4], o[4][4];
#pragma unroll
    for (int i = 0; i < 4; i++) {
        m_i[i] = -3.0e38f;
        l_i[i] = 0.0f;
#pragma unroll
        for (int j = 0; j < 4; j++) o[i][j] = 0.0f;
    }
    __syncthreads();

    for (int kt = 0; kt < SEQ / 64; kt++) {
        const int kbase = kt * 64;

        // Load K (transposed) and V (natural) tiles + mask
#pragma unroll
        for (int p = 0; p < 16; p++) {
            int idx = tid + p * 256;
            int r = idx >> 6, d = idx & 63;
            float kv = Kp[(size_t)kbase * DK + idx];
            float vv = Vp[(size_t)kbase * DK + idx];
            Ks[d * ASTR + r] = kv;
            Vs[r * ASTR + d] = vv;
        }
        if (tid < 64)
            mk[tid] = (mask[b * SEQ + kbase + tid] == 0) ? -1.0e9f : 0.0f;
        __syncthreads();

        // S = Q K^T (per-thread 4x4)
        float s[4][4];
#pragma unroll
        for (int i = 0; i < 4; i++)
#pragma unroll
            for (int j = 0; j < 4; j++) s[i][j] = 0.0f;

#pragma unroll 8
        for (int kk = 0; kk < 64; kk++) {
            float4 a4 = *(const float4*)&Qs[kk * ASTR + ty * 4];
            float4 b4 = *(const float4*)&Ks[kk * ASTR + tx * 4];
            float a[4] = {a4.x, a4.y, a4.z, a4.w};
            float bb[4] = {b4.x, b4.y, b4.z, b4.w};
#pragma unroll
            for (int i = 0; i < 4; i++)
#pragma unroll
                for (int j = 0; j < 4; j++) s[i][j] += a[i] * bb[j];
        }
        __syncthreads();  // Ks reads done; safe to overwrite with P

        // scale + mask
#pragma unroll
        for (int j = 0; j < 4; j++) {
            float mv = mk[tx * 4 + j];
#pragma unroll
            for (int i = 0; i < 4; i++) s[i][j] = s[i][j] * 0.125f + mv;
        }

        // online softmax per row (rows owned by 16-lane tx-groups)
#pragma unroll
        for (int i = 0; i < 4; i++) {
            float rm = fmaxf(fmaxf(s[i][0], s[i][1]), fmaxf(s[i][2], s[i][3]));
            rm = fmaxf(rm, __shfl_xor_sync(0xffffffffu, rm, 8));
            rm = fmaxf(rm, __shfl_xor_sync(0xffffffffu, rm, 4));
            rm = fmaxf(rm, __shfl_xor_sync(0xffffffffu, rm, 2));
            rm = fmaxf(rm, __shfl_xor_sync(0xffffffffu, rm, 1));
            float mn = fmaxf(m_i[i], rm);
            float corr = __expf(m_i[i] - mn);
            m_i[i] = mn;
            float rs = 0.0f;
#pragma unroll
            for (int j = 0; j < 4; j++) {
                float pv = __expf(s[i][j] - mn);
                s[i][j] = pv;
                rs += pv;
            }
            rs += __shfl_xor_sync(0xffffffffu, rs, 8);
            rs += __shfl_xor_sync(0xffffffffu, rs, 4);
            rs += __shfl_xor_sync(0xffffffffu, rs, 2);
            rs += __shfl_xor_sync(0xffffffffu, rs, 1);
            l_i[i] = l_i[i] * corr + rs;
#pragma unroll
            for (int j = 0; j < 4; j++) {
                o[i][j] *= corr;
                // write P transposed: Ps[kc][row], kc = tx*4+j, row = ty*4+i
                Ks[(tx * 4 + j) * ASTR + ty * 4 + i] = s[i][j];
            }
        }
        __syncthreads();

        // O += P @ V
#pragma unroll 8
        for (int kk = 0; kk < 64; kk++) {
            float4 a4 = *(const float4*)&Ks[kk * ASTR + ty * 4];  // P[kc][rows]
            float4 b4 = *(const float4*)&Vs[kk * ASTR + tx * 4];  // V[kc][d]
            float a[4] = {a4.x, a4.y, a4.z, a4.w};
            float bb[4] = {b4.x, b4.y, b4.z, b4.w};
#pragma unroll
            for (int i = 0; i < 4; i++)
#pragma unroll
                for (int j = 0; j < 4; j++) o[i][j] += a[i] * bb[j];
        }
        __syncthreads();
    }

    // epilogue: O /= l, write ctx[b, s, h*64 + d]
#pragma unroll
    for (int i = 0; i < 4; i++) {
        float inv = 1.0f / l_i[i];
        int row = qbase + ty * 4 + i;
        size_t base = ((size_t)b * SEQ + row) * D_MODEL + h * DK;
#pragma unroll
        for (int j = 0; j < 4; j++) {
            ctx[base + tx * 4 + j] = o[i][j] * inv;
        }
    }
}

// ---------------------------------------------------------------------------
// Launch
// ---------------------------------------------------------------------------
extern "C" void kernel_launch(void* const* d_in, const int* in_sizes, int n_in,
                              void* d_out, int out_size) {
    (void)in_sizes; (void)n_in; (void)out_size;
    const float* q    = (const float*)d_in[0];
    const float* k    = (const float*)d_in[1];
    const float* v    = (const float*)d_in[2];
    const int*   mask = (const int*)d_in[3];
    const float* Wq   = (const float*)d_in[4];
    const float* bq   = (const float*)d_in[5];
    const float* Wk   = (const float*)d_in[6];
    const float* bk   = (const float*)d_in[7];
    const float* Wv   = (const float*)d_in[8];
    const float* bv   = (const float*)d_in[9];
    const float* Wo   = (const float*)d_in[10];
    const float* bo   = (const float*)d_in[11];
    float* out = (float*)d_out;

    void *pqh, *pkh, *pvh, *pctx;
    cudaGetSymbolAddress(&pqh, g_qh);
    cudaGetSymbolAddress(&pkh, g_kh);
    cudaGetSymbolAddress(&pvh, g_vh);
    cudaGetSymbolAddress(&pctx, g_ctx);

    const int M = BATCH * SEQ;     // 4096
    const int N = D_MODEL;         // 1024
    const int K = D_MODEL;         // 1024

    dim3 gGrid(M / BM, N / BN);    // (64, 16)
    dim3 gBlk(256);

    // Projections -> head layout
    gemm_nt<<<gGrid, gBlk>>>(q, Wq, bq, (float*)pqh, M, N, K, 1);
    gemm_nt<<<gGrid, gBlk>>>(k, Wk, bk, (float*)pkh, M, N, K, 1);
    gemm_nt<<<gGrid, gBlk>>>(v, Wv, bv, (float*)pvh, M, N, K, 1);

    // Attention
    const int smemBytes = (3 * 64 * ASTR + 64) * (int)sizeof(float);  // 52480
    cudaFuncSetAttribute(attn_kernel, cudaFuncAttributeMaxDynamicSharedMemorySize,
                         smemBytes);
    dim3 aGrid(SEQ / 64, BATCH * NUM_HEADS);  // (32, 32)
    attn_kernel<<<aGrid, gBlk, smemBytes>>>((const float*)pqh, (const float*)pkh,
                                            (const float*)pvh, mask, (float*)pctx);

    // Output projection
    gemm_nt<<<gGrid, gBlk>>>((const float*)pctx, Wo, bo, out, M, N, K, 0);
}